// round 2
// baseline (speedup 1.0000x reference)
#include <cuda_runtime.h>
#include <math.h>

#define T_DIM 8000
#define F_DIM 80
#define B_DIM 64
#define NV4   2000          // float4s per row
#define NTHREADS 256
#define V_PER_THREAD 8      // ceil(2000/256)
#define EPS 1e-10f

__global__ __launch_bounds__(NTHREADS)
void isn_kernel(const float* __restrict__ x,
                const float* __restrict__ lengths,
                float* __restrict__ out)
{
    const int f = blockIdx.x;
    const int b = blockIdx.y;
    const size_t row_off = (size_t)(b * F_DIM + f) * T_DIM;
    const float4* __restrict__ row  = reinterpret_cast<const float4*>(x + row_off);
    float4*       __restrict__ orow = reinterpret_cast<float4*>(out + row_off);

    // n = round(lengths[b] * T), round-half-to-even to match jnp.round
    const int n = (int)rintf(lengths[b] * (float)T_DIM);

    const int tid = threadIdx.x;

    // ---- Pass 1: load row into registers, masked accumulate sum / sumsq ----
    float4 v[V_PER_THREAD];
    float s = 0.0f, ss = 0.0f;

#pragma unroll
    for (int i = 0; i < V_PER_THREAD; i++) {
        const int idx = tid + i * NTHREADS;          // float4 index
        if (idx < NV4) {
            v[i] = row[idx];
            const int e = idx * 4;                   // element index of .x
            float a;
            a = (e + 0 < n) ? v[i].x : 0.0f; s += a; ss += a * a;
            a = (e + 1 < n) ? v[i].y : 0.0f; s += a; ss += a * a;
            a = (e + 2 < n) ? v[i].z : 0.0f; s += a; ss += a * a;
            a = (e + 3 < n) ? v[i].w : 0.0f; s += a; ss += a * a;
        }
    }

    // ---- Block reduction (8 warps) ----
#pragma unroll
    for (int off = 16; off > 0; off >>= 1) {
        s  += __shfl_down_sync(0xFFFFFFFFu, s,  off);
        ss += __shfl_down_sync(0xFFFFFFFFu, ss, off);
    }

    __shared__ float sh_s[NTHREADS / 32];
    __shared__ float sh_ss[NTHREADS / 32];
    __shared__ float sh_mean, sh_rstd;

    const int lane = tid & 31;
    const int wid  = tid >> 5;
    if (lane == 0) { sh_s[wid] = s; sh_ss[wid] = ss; }
    __syncthreads();

    if (tid == 0) {
        float ts = 0.0f, tss = 0.0f;
#pragma unroll
        for (int w = 0; w < NTHREADS / 32; w++) { ts += sh_s[w]; tss += sh_ss[w]; }
        const float nf   = (float)n;
        const float mean = ts / nf;
        const float var  = (tss - ts * mean) / (nf - 1.0f);
        const float std_ = fmaxf(sqrtf(fmaxf(var, 0.0f)), EPS);
        sh_mean = mean;
        sh_rstd = 1.0f / std_;
    }
    __syncthreads();

    const float mean = sh_mean;
    const float rstd = sh_rstd;

    // ---- Pass 2: normalize from registers, vectorized store ----
#pragma unroll
    for (int i = 0; i < V_PER_THREAD; i++) {
        const int idx = tid + i * NTHREADS;
        if (idx < NV4) {
            float4 o;
            o.x = (v[i].x - mean) * rstd;
            o.y = (v[i].y - mean) * rstd;
            o.z = (v[i].z - mean) * rstd;
            o.w = (v[i].w - mean) * rstd;
            orow[idx] = o;
        }
    }
}

extern "C" void kernel_launch(void* const* d_in, const int* in_sizes, int n_in,
                              void* d_out, int out_size)
{
    const float* x       = (const float*)d_in[0];
    const float* lengths = (const float*)d_in[1];
    float*       out     = (float*)d_out;

    dim3 grid(F_DIM, B_DIM);
    isn_kernel<<<grid, NTHREADS>>>(x, lengths, out);
}

// round 6
// speedup vs baseline: 1.0090x; 1.0090x over previous
#include <cuda_runtime.h>
#include <math.h>

#define T_DIM 8000
#define F_DIM 80
#define B_DIM 64
#define NV4   2000          // float4s per row
#define NTHREADS 512
#define V_PER_THREAD 4      // ceil(2000/512)
#define NWARPS (NTHREADS / 32)
#define EPS 1e-10f

__global__ __launch_bounds__(NTHREADS)
void isn_kernel(const float* __restrict__ x,
                const float* __restrict__ lengths,
                float* __restrict__ out)
{
    const int f = blockIdx.x;
    const int b = blockIdx.y;
    const size_t row_off = (size_t)(b * F_DIM + f) * T_DIM;
    const float4* __restrict__ row  = reinterpret_cast<const float4*>(x + row_off);
    float4*       __restrict__ orow = reinterpret_cast<float4*>(out + row_off);

    // n = round(lengths[b] * T), round-half-to-even to match jnp.round
    const int n = (int)rintf(lengths[b] * (float)T_DIM);

    const int tid = threadIdx.x;

    // ---- Pass 1: load row into registers (streaming), masked accumulate ----
    float4 v[V_PER_THREAD];
    float s = 0.0f, ss = 0.0f;

#pragma unroll
    for (int i = 0; i < V_PER_THREAD; i++) {
        const int idx = tid + i * NTHREADS;          // float4 index
        if (idx < NV4) {
            v[i] = __ldcs(&row[idx]);
        }
    }

#pragma unroll
    for (int i = 0; i < V_PER_THREAD; i++) {
        const int idx = tid + i * NTHREADS;
        if (idx < NV4) {
            const int e = idx * 4;                   // element index of .x
            if (e + 3 < n) {
                // fully valid vector — no masking needed
                s  += v[i].x + v[i].y + v[i].z + v[i].w;
                ss += v[i].x * v[i].x + v[i].y * v[i].y
                    + v[i].z * v[i].z + v[i].w * v[i].w;
            } else {
                float a;
                a = (e + 0 < n) ? v[i].x : 0.0f; s += a; ss += a * a;
                a = (e + 1 < n) ? v[i].y : 0.0f; s += a; ss += a * a;
                a = (e + 2 < n) ? v[i].z : 0.0f; s += a; ss += a * a;
                a = (e + 3 < n) ? v[i].w : 0.0f; s += a; ss += a * a;
            }
        }
    }

    // ---- Block reduction (16 warps) ----
#pragma unroll
    for (int off = 16; off > 0; off >>= 1) {
        s  += __shfl_down_sync(0xFFFFFFFFu, s,  off);
        ss += __shfl_down_sync(0xFFFFFFFFu, ss, off);
    }

    __shared__ float sh_s[NWARPS];
    __shared__ float sh_ss[NWARPS];
    __shared__ float sh_mean, sh_rstd;

    const int lane = tid & 31;
    const int wid  = tid >> 5;
    if (lane == 0) { sh_s[wid] = s; sh_ss[wid] = ss; }
    __syncthreads();

    if (tid == 0) {
        float ts = 0.0f, tss = 0.0f;
#pragma unroll
        for (int w = 0; w < NWARPS; w++) { ts += sh_s[w]; tss += sh_ss[w]; }
        const float nf   = (float)n;
        const float mean = ts / nf;
        const float var  = (tss - ts * mean) / (nf - 1.0f);
        const float std_ = fmaxf(sqrtf(fmaxf(var, 0.0f)), EPS);
        sh_mean = mean;
        sh_rstd = 1.0f / std_;
    }
    __syncthreads();

    const float mean = sh_mean;
    const float rstd = sh_rstd;

    // ---- Pass 2: normalize from registers, streaming vectorized store ----
#pragma unroll
    for (int i = 0; i < V_PER_THREAD; i++) {
        const int idx = tid + i * NTHREADS;
        if (idx < NV4) {
            float4 o;
            o.x = (v[i].x - mean) * rstd;
            o.y = (v[i].y - mean) * rstd;
            o.z = (v[i].z - mean) * rstd;
            o.w = (v[i].w - mean) * rstd;
            __stcs(&orow[idx], o);
        }
    }
}

extern "C" void kernel_launch(void* const* d_in, const int* in_sizes, int n_in,
                              void* d_out, int out_size)
{
    const float* x       = (const float*)d_in[0];
    const float* lengths = (const float*)d_in[1];
    float*       out     = (float*)d_out;

    dim3 grid(F_DIM, B_DIM);
    isn_kernel<<<grid, NTHREADS>>>(x, lengths, out);
}